// round 17
// baseline (speedup 1.0000x reference)
#include <cuda_runtime.h>
#include <cuda_fp16.h>
#include <cstdint>

#define B_    16
#define CIN_  256
#define COUT_ 256
#define H_    64
#define W_    64
#define SDIM_ 512

#define MOD_SCALE (1.0f / 48.0f)
#define SCALE2    (1.0f / 2304.0f)

// scratch
__device__ float g_s[B_ * CIN_];
__device__ float g_demod[B_ * COUT_];
__device__ float g_wsq[COUT_ * CIN_];
__device__ __half g_wth[(size_t)9 * COUT_ * CIN_];        // [tap][co][ci], batch-free
__device__ __half g_xh[(size_t)B_ * H_ * W_ * CIN_];      // NHWC fp16 of x * s[b,ci]

__device__ __forceinline__ uint32_t h2_bits(__half2 h) {
    union { __half2 h; uint32_t u; } c;
    c.h = h;
    return c.u;
}

// ---------------------------------------------------------------------------
// K_wcvt: fused batch-free weight convert + wsq. grid (32), block 256.
__global__ void k_wcvt(const float* __restrict__ weight) {
    const int tid = threadIdx.x;
    const int co = blockIdx.x * 8 + (tid >> 5);
    const int oct = tid & 31;

    float w[72];
    {
        const float4* wp = (const float4*)(weight + (size_t)co * 2304 + oct * 72);
        #pragma unroll
        for (int i = 0; i < 18; i++) {
            float4 v = wp[i];
            w[i * 4 + 0] = v.x; w[i * 4 + 1] = v.y; w[i * 4 + 2] = v.z; w[i * 4 + 3] = v.w;
        }
    }
    __half* ob = g_wth + (size_t)co * CIN_ + oct * 8;
    #pragma unroll
    for (int tap = 0; tap < 9; tap++) {
        uint32_t u[4];
        #pragma unroll
        for (int j2 = 0; j2 < 4; j2++) {
            u[j2] = h2_bits(__floats2half2_rn(w[(2 * j2) * 9 + tap],
                                              w[(2 * j2 + 1) * 9 + tap]));
        }
        *(uint4*)(ob + (size_t)tap * COUT_ * CIN_) = make_uint4(u[0], u[1], u[2], u[3]);
    }
    float q[8];
    #pragma unroll
    for (int j = 0; j < 8; j++) {
        float s = 0.f;
        #pragma unroll
        for (int t = 0; t < 9; t++) { float v = w[j * 9 + t]; s += v * v; }
        q[j] = s;
    }
    float4* wq = (float4*)(g_wsq + co * CIN_ + oct * 8);
    wq[0] = make_float4(q[0], q[1], q[2], q[3]);
    wq[1] = make_float4(q[4], q[5], q[6], q[7]);
}

// ---------------------------------------------------------------------------
// K_sd: fused style projection + demod. grid = B_, block = 256.
__global__ void k_sproj_demod(const float* __restrict__ style,
                              const float* __restrict__ style_w,
                              const float* __restrict__ style_b) {
    __shared__ float st[SDIM_];
    __shared__ float s2[CIN_];
    const int b = blockIdx.x, tid = threadIdx.x;
    for (int k = tid; k < SDIM_; k += 256)
        st[k] = style[b * SDIM_ + k];
    __syncthreads();
    float acc = style_b[tid];
    #pragma unroll 8
    for (int k = 0; k < SDIM_; k++)
        acc += st[k] * style_w[k * CIN_ + tid];
    g_s[b * CIN_ + tid] = acc;
    s2[tid] = acc * acc;
    __syncthreads();
    float acc2 = 0.f;
    const float* wq = g_wsq + tid * CIN_;
    #pragma unroll 8
    for (int ci = 0; ci < CIN_; ci++)
        acc2 += s2[ci] * wq[ci];
    g_demod[b * COUT_ + tid] = rsqrtf(acc2 * SCALE2 + 1e-8f);
}

// ---------------------------------------------------------------------------
// K_xcvt: NCHW fp32 -> NHWC fp16, folding in s[b,ci]; ci-pair half2 transpose.
#define XPAD 72
__global__ void __launch_bounds__(256)
k_xcvt(const float* __restrict__ x) {
    __shared__ __half xsp[64 * XPAD];
    __shared__ float sS[64];
    const int b = blockIdx.z, h = blockIdx.y, ci0 = blockIdx.x * 64;
    const int tid = threadIdx.x;
    const float* xp = x + ((size_t)(b * CIN_ + ci0) * H_ + h) * W_;

    if (tid < 64) sS[tid] = g_s[b * CIN_ + ci0 + tid];
    __syncthreads();

    #pragma unroll
    for (int i = 0; i < 8; i++) {
        int idx = tid + i * 256;                // 0..2047
        int cp = idx >> 6, w = idx & 63;
        int ci = cp * 2;
        float v0 = xp[(size_t)ci * (H_ * W_) + w] * sS[ci];
        float v1 = xp[(size_t)(ci + 1) * (H_ * W_) + w] * sS[ci + 1];
        *(__half2*)&xsp[w * XPAD + ci] = __floats2half2_rn(v0, v1);
    }
    __syncthreads();

    __half* op = g_xh + (((size_t)b * H_ + h) * W_) * CIN_ + ci0;
    #pragma unroll
    for (int i = 0; i < 2; i++) {
        int idx = tid + i * 256;
        int w = idx >> 3, j = idx & 7;
        uint4 v = *(const uint4*)&xsp[w * XPAD + j * 8];
        *(uint4*)(op + (size_t)w * CIN_ + j * 8) = v;
    }
}

// ---------------------------------------------------------------------------
// K_conv: 3-stage-pipelined implicit-GEMM + tap-level fragment double-buffer.
// CTA tile: M=64 co x N=128 px. 8 warps = 2M x 4N, warp 32co x 32px.
// grid (32, 4, 16), block 256.
#define KC 16
#define NC (CIN_ / KC)                 // 16 chunks
#define XS_BYTES (264 * KC * 2)        // 8448
#define WS_BYTES (9 * 64 * KC * 2)     // 18432
#define STAGE_BYTES (XS_BYTES + WS_BYTES)   // 26880
#define SMEM_TOTAL (3 * STAGE_BYTES)        // 80640

__global__ void __launch_bounds__(256, 2)
k_conv(float* __restrict__ out) {
    extern __shared__ char smem[];
    const uint32_t smem_u = (uint32_t)__cvta_generic_to_shared(smem);

    const int tid = threadIdx.x;
    const int lane = tid & 31, wid = tid >> 5;
    const int warp_m = wid >> 2;           // 0..1
    const int warp_n = wid & 3;            // 0..3
    const int g = lane >> 2, tig = lane & 3;

    const int h0 = blockIdx.x * 2;
    const int co_base = blockIdx.y * 64;
    const int b = blockIdx.z;

    const __half* wtb = g_wth + (size_t)co_base * CIN_;
    const __half* xhb = g_xh + (size_t)b * H_ * W_ * CIN_;

    // B staging geometry
    const int co_t = tid >> 1, hl = tid & 1;
    uint32_t b_goff[3];
    int b_sz[3];
    #pragma unroll
    for (int k = 0; k < 3; k++) {
        int px = co_t + k * 128;
        int r = px / 66, cc = px - r * 66;
        int gh = h0 - 1 + r, gw = cc - 1;
        bool ok = ((unsigned)gh < (unsigned)H_) && ((unsigned)gw < (unsigned)W_);
        int ghc = ok ? gh : 0, gwc = ok ? gw : 0;
        b_goff[k] = (uint32_t)((ghc * W_ + gwc) * CIN_ + hl * 8);
        b_sz[k] = ok ? 16 : 0;
    }
    const uint32_t swzB = (uint32_t)((hl ^ ((co_t >> 2) & 1)) << 4);

    float acc[2][4][4];
    #pragma unroll
    for (int mt = 0; mt < 2; mt++)
        #pragma unroll
        for (int nt = 0; nt < 4; nt++)
            #pragma unroll
            for (int q = 0; q < 4; q++) acc[mt][nt][q] = 0.f;

    auto issue = [&](int c, int s) {
        const uint32_t stage = smem_u + s * STAGE_BYTES;
        #pragma unroll
        for (int j = 0; j < 5; j++) {
            int u = tid + j * 256;
            if (j < 4 || u < 1152) {
                int row = u >> 1, ah = u & 1;       // row = tap*64+co
                int tap = row >> 6, co = row & 63;
                const __half* src = wtb + ((size_t)tap * COUT_ + co) * CIN_ + c * KC + ah * 8;
                uint32_t dst = stage + XS_BYTES + row * 32 + ((ah ^ ((co >> 2) & 1)) << 4);
                asm volatile("cp.async.cg.shared.global [%0], [%1], 16;"
                             :: "r"(dst), "l"(src));
            }
        }
        const __half* bsrc = xhb + c * KC;
        const uint32_t xsu = stage + co_t * 32 + swzB;
        #pragma unroll
        for (int k = 0; k < 2; k++) {
            asm volatile("cp.async.cg.shared.global [%0], [%1], 16, %2;"
                         :: "r"(xsu + k * 4096), "l"(bsrc + b_goff[k]), "r"(b_sz[k]));
        }
        if (tid < 16) {
            asm volatile("cp.async.cg.shared.global [%0], [%1], 16, %2;"
                         :: "r"(xsu + 2 * 4096), "l"(bsrc + b_goff[2]), "r"(b_sz[2]));
        }
        asm volatile("cp.async.commit_group;");
    };

    issue(0, 0);
    issue(1, 1);

    // ldmatrix lane geometry (A vs B distinct)
    const int laneRowA = (lane & 7) + (((lane >> 3) & 1) << 3);
    const uint32_t kA = (uint32_t)(((lane >> 4) & 1) << 4);
    const int laneRowB = (lane & 7) + ((lane >> 4) << 3);
    const uint32_t kB = (uint32_t)(((lane >> 3) & 1) << 4);

    const int rB = warp_n >> 1;
    const int cB = (warp_n & 1) * 32;

    // tap-level fragment double buffers
    uint32_t aF[2][2][4];
    uint32_t bF[2][2][4];

    int sc = 0;
    for (int c = 0; c < NC; c++) {
        __syncthreads();
        int s2 = sc + 2; if (s2 >= 3) s2 -= 3;
        if (c + 2 < NC) {
            issue(c + 2, s2);
            asm volatile("cp.async.wait_group 2;" ::: "memory");
        } else if (c + 1 < NC) {
            asm volatile("cp.async.wait_group 1;" ::: "memory");
        } else {
            asm volatile("cp.async.wait_group 0;" ::: "memory");
        }

        const uint32_t xs_u2 = smem_u + sc * STAGE_BYTES;
        const uint32_t ws_u2 = xs_u2 + XS_BYTES;

        // load tap 0 fragments into buffer 0
        {
            #pragma unroll
            for (int mt = 0; mt < 2; mt++) {
                int rowA = warp_m * 32 + mt * 16 + laneRowA;   // tap 0
                uint32_t addrA = ws_u2 + rowA * 32 + (kA ^ ((rowA & 4) << 2));
                asm volatile("ldmatrix.sync.aligned.m8n8.x4.shared.b16 "
                             "{%0,%1,%2,%3}, [%4];"
                             : "=r"(aF[0][mt][0]), "=r"(aF[0][mt][1]),
                               "=r"(aF[0][mt][2]), "=r"(aF[0][mt][3])
                             : "r"(addrA));
            }
            const int rowoff0 = rB * 66 + cB;                  // dh=0, dw=0
            #pragma unroll
            for (int ntp = 0; ntp < 2; ntp++) {
                int pxl = rowoff0 + ntp * 16 + laneRowB;
                uint32_t addrB = xs_u2 + pxl * 32 + (kB ^ ((pxl & 4) << 2));
                asm volatile("ldmatrix.sync.aligned.m8n8.x4.shared.b16 "
                             "{%0,%1,%2,%3}, [%4];"
                             : "=r"(bF[0][ntp][0]), "=r"(bF[0][ntp][1]),
                               "=r"(bF[0][ntp][2]), "=r"(bF[0][ntp][3])
                             : "r"(addrB));
            }
        }

        #pragma unroll
        for (int tap = 0; tap < 9; tap++) {
            const int cur = tap & 1, nxt = cur ^ 1;
            // prefetch tap+1 fragments while computing tap
            if (tap < 8) {
                const int t2 = tap + 1;
                const int dh2 = t2 / 3, dw2 = t2 - dh2 * 3;
                #pragma unroll
                for (int mt = 0; mt < 2; mt++) {
                    int rowA = t2 * 64 + warp_m * 32 + mt * 16 + laneRowA;
                    uint32_t addrA = ws_u2 + rowA * 32 + (kA ^ ((rowA & 4) << 2));
                    asm volatile("ldmatrix.sync.aligned.m8n8.x4.shared.b16 "
                                 "{%0,%1,%2,%3}, [%4];"
                                 : "=r"(aF[nxt][mt][0]), "=r"(aF[nxt][mt][1]),
                                   "=r"(aF[nxt][mt][2]), "=r"(aF[nxt][mt][3])
                                 : "r"(addrA));
                }
                const int rowoff = (rB + dh2) * 66 + dw2 + cB;
                #pragma unroll
                for (int ntp = 0; ntp < 2; ntp++) {
                    int pxl = rowoff + ntp * 16 + laneRowB;
                    uint32_t addrB = xs_u2 + pxl * 32 + (kB ^ ((pxl & 4) << 2));
                    asm volatile("ldmatrix.sync.aligned.m8n8.x4.shared.b16 "
                                 "{%0,%1,%2,%3}, [%4];"
                                 : "=r"(bF[nxt][ntp][0]), "=r"(bF[nxt][ntp][1]),
                                   "=r"(bF[nxt][ntp][2]), "=r"(bF[nxt][ntp][3])
                                 : "r"(addrB));
                }
            }
            // 16 mma on current buffer
            #pragma unroll
            for (int ntp = 0; ntp < 2; ntp++) {
                #pragma unroll
                for (int half = 0; half < 2; half++) {
                    int nt = ntp * 2 + half;
                    #pragma unroll
                    for (int mt = 0; mt < 2; mt++) {
                        asm volatile(
                            "mma.sync.aligned.m16n8k16.row.col.f32.f16.f16.f32 "
                            "{%0,%1,%2,%3}, {%4,%5,%6,%7}, {%8,%9}, {%0,%1,%2,%3};\n"
                            : "+f"(acc[mt][nt][0]), "+f"(acc[mt][nt][1]),
                              "+f"(acc[mt][nt][2]), "+f"(acc[mt][nt][3])
                            : "r"(aF[cur][mt][0]), "r"(aF[cur][mt][1]),
                              "r"(aF[cur][mt][2]), "r"(aF[cur][mt][3]),
                              "r"(bF[cur][ntp][half * 2]), "r"(bF[cur][ntp][half * 2 + 1]));
                    }
                }
            }
        }
        sc = (sc + 1 == 3) ? 0 : sc + 1;
    }

    // epilogue
    const int h = h0 + rB;
    #pragma unroll
    for (int mt = 0; mt < 2; mt++) {
        int co_lo = co_base + warp_m * 32 + mt * 16 + g;
        float f0 = MOD_SCALE * __ldg(&g_demod[b * COUT_ + co_lo]);
        float f1 = MOD_SCALE * __ldg(&g_demod[b * COUT_ + co_lo + 8]);
        #pragma unroll
        for (int nt = 0; nt < 4; nt++) {
            int w = cB + nt * 8 + tig * 2;
            float* p0 = out + (((size_t)(b * COUT_ + co_lo)) * H_ + h) * W_ + w;
            *(float2*)p0 = make_float2(acc[mt][nt][0] * f0, acc[mt][nt][1] * f0);
            float* p1 = p0 + (size_t)8 * H_ * W_;
            *(float2*)p1 = make_float2(acc[mt][nt][2] * f1, acc[mt][nt][3] * f1);
        }
    }
}

// ---------------------------------------------------------------------------
extern "C" void kernel_launch(void* const* d_in, const int* in_sizes, int n_in,
                              void* d_out, int out_size) {
    const float* x       = (const float*)d_in[0];
    const float* style   = (const float*)d_in[1];
    const float* weight  = (const float*)d_in[2];
    const float* style_w = (const float*)d_in[3];
    const float* style_b = (const float*)d_in[4];
    float* out = (float*)d_out;

    cudaFuncSetAttribute(k_conv, cudaFuncAttributeMaxDynamicSharedMemorySize, SMEM_TOTAL);

    k_wcvt<<<32, 256>>>(weight);
    k_sproj_demod<<<B_, 256>>>(style, style_w, style_b);

    dim3 gx(4, 64, 16);
    k_xcvt<<<gx, 256>>>(x);

    dim3 gc(32, 4, 16);
    k_conv<<<gc, 256, SMEM_TOTAL>>>(out);
}